// round 7
// baseline (speedup 1.0000x reference)
#include <cuda_runtime.h>
#include <cuda_fp16.h>
#include <math.h>
#include <stdint.h>

#define DIM   2048
#define INTER 1408
#define NE    15
#define TMAX  4096
#define KC    32
// stage layout (bytes): AH[0,8K) AL[8K,16K) BH[16K,24K)
#define STAGE 24576
#define NST   4

// ---------------- device scratch ----------------
__device__ int   g_count[NE];
__device__ int   g_offset[NE + 1];
__device__ int   g_tok[NE * TMAX];
__device__ float g_wt[NE * TMAX];
__device__ int   g_exp[2 * TMAX];
__device__ int   g_pos[2 * TMAX];
__device__ __half g_xh[(size_t)TMAX * DIM];
__device__ __half g_xl[(size_t)TMAX * DIM];
__device__ __half g_w1h[(size_t)NE * INTER * DIM];
__device__ __half g_w3h[(size_t)NE * INTER * DIM];
__device__ __half g_w2h[(size_t)NE * DIM * INTER];
__device__ __half g_sw1h[(size_t)INTER * DIM];
__device__ __half g_sw3h[(size_t)INTER * DIM];
__device__ __half g_sw2h[(size_t)DIM * INTER];
__device__ __half g_hh[(size_t)3 * TMAX * INTER];
__device__ __half g_hl[(size_t)3 * TMAX * INTER];
__device__ float  g_d[(size_t)3 * TMAX * DIM];   // down results, compacted rows

// ---------------- helpers ----------------
__device__ __forceinline__ uint32_t smem_u32(const void* p) {
    uint32_t a;
    asm("{ .reg .u64 t; cvta.to.shared.u64 t, %1; cvt.u32.u64 %0, t; }" : "=r"(a) : "l"(p));
    return a;
}
// swizzled byte offset inside a 128x32 fp16 tile (64B rows, 4 chunks of 16B)
__device__ __forceinline__ uint32_t toff(uint32_t r, uint32_t c) {
    return r * 64u + ((c ^ ((r >> 1) & 3u)) << 4);
}
__device__ __forceinline__ void ldsm4(uint32_t r[4], uint32_t a) {
    asm volatile("ldmatrix.sync.aligned.m8n8.x4.shared.b16 {%0,%1,%2,%3},[%4];"
                 : "=r"(r[0]), "=r"(r[1]), "=r"(r[2]), "=r"(r[3]) : "r"(a));
}
__device__ __forceinline__ void mma_f16(float c[4], const uint32_t a[4], const uint32_t b[2]) {
    asm volatile("mma.sync.aligned.m16n8k16.row.col.f32.f16.f16.f32 "
                 "{%0,%1,%2,%3},{%4,%5,%6,%7},{%8,%9},{%0,%1,%2,%3};"
                 : "+f"(c[0]), "+f"(c[1]), "+f"(c[2]), "+f"(c[3])
                 : "r"(a[0]), "r"(a[1]), "r"(a[2]), "r"(a[3]), "r"(b[0]), "r"(b[1]));
}
__device__ __forceinline__ void cpa16(uint32_t s, const void* g) {
    asm volatile("cp.async.cg.shared.global [%0], [%1], 16;" :: "r"(s), "l"(g));
}
__device__ __forceinline__ void cpcommit() { asm volatile("cp.async.commit_group;"); }
template <int N> __device__ __forceinline__ void cpwait() {
    asm volatile("cp.async.wait_group %0;" :: "n"(N));
}

// one k-chunk, 2-term split: c += ah*bh + al*bh
__device__ __forceinline__ void compute_iter2(float acc[2][8][4], uint32_t base,
                                              int wm, int wn, int arow, int asel,
                                              int brow, int bsel) {
#pragma unroll
    for (int ks = 0; ks < 2; ks++) {
        uint32_t ah[2][4], al[2][4];
#pragma unroll
        for (int mt = 0; mt < 2; mt++) {
            uint32_t ao = toff((uint32_t)(wm + mt * 16 + arow), (uint32_t)(ks * 2 + asel));
            ldsm4(ah[mt], base + ao);
            ldsm4(al[mt], base + 8192 + ao);
        }
#pragma unroll
        for (int np = 0; np < 4; np++) {
            uint32_t bo = toff((uint32_t)(wn + np * 16 + brow), (uint32_t)(ks * 2 + bsel));
            uint32_t bh[4];
            ldsm4(bh, base + 16384 + bo);
#pragma unroll
            for (int mt = 0; mt < 2; mt++)
#pragma unroll
                for (int ns = 0; ns < 2; ns++) {
                    float* c = acc[mt][np * 2 + ns];
                    mma_f16(c, ah[mt], bh + ns * 2);
                    mma_f16(c, al[mt], bh + ns * 2);
                }
        }
    }
}

// ---------------- converts ----------------
__global__ void cvt_hi_kernel(const float4* __restrict__ in, uint2* __restrict__ hi, int n4) {
    int i = blockIdx.x * 256 + threadIdx.x;
    if (i >= n4) return;
    float4 v = in[i];
    __half2 a = __floats2half2_rn(v.x, v.y), b = __floats2half2_rn(v.z, v.w);
    hi[i] = make_uint2(*(uint32_t*)&a, *(uint32_t*)&b);
}
__global__ void cvt_hilo_kernel(const float4* __restrict__ in, uint2* __restrict__ hi,
                                uint2* __restrict__ lo, int n4) {
    int i = blockIdx.x * 256 + threadIdx.x;
    if (i >= n4) return;
    float4 v = in[i];
    __half2 a = __floats2half2_rn(v.x, v.y), b = __floats2half2_rn(v.z, v.w);
    float2 fa = __half22float2(a), fb = __half22float2(b);
    __half2 la = __floats2half2_rn(v.x - fa.x, v.y - fa.y);
    __half2 lb = __floats2half2_rn(v.z - fb.x, v.w - fb.y);
    hi[i] = make_uint2(*(uint32_t*)&a, *(uint32_t*)&b);
    lo[i] = make_uint2(*(uint32_t*)&la, *(uint32_t*)&lb);
}

// ---------------- gating ----------------
__global__ void reset_kernel() { if (threadIdx.x < NE) g_count[threadIdx.x] = 0; }

__global__ void gate_kernel(const float* __restrict__ x,
                            const float* __restrict__ gw, int T) {
    int t = blockIdx.x;
    const float* xt = x + (size_t)t * DIM;
    float acc[NE];
#pragma unroll
    for (int e = 0; e < NE; e++) acc[e] = 0.f;
    for (int d = threadIdx.x; d < DIM; d += 128) {
        float xv = xt[d];
#pragma unroll
        for (int e = 0; e < NE; e++) acc[e] += xv * gw[e * DIM + d];
    }
#pragma unroll
    for (int e = 0; e < NE; e++)
        for (int o = 16; o > 0; o >>= 1)
            acc[e] += __shfl_down_sync(0xffffffffu, acc[e], o);
    __shared__ float s[NE][4];
    int lane = threadIdx.x & 31, w = threadIdx.x >> 5;
    if (lane == 0) {
#pragma unroll
        for (int e = 0; e < NE; e++) s[e][w] = acc[e];
    }
    __syncthreads();
    if (threadIdx.x == 0) {
        float v[NE], p[NE];
        float mx = -1e30f;
#pragma unroll
        for (int e = 0; e < NE; e++) {
            v[e] = s[e][0] + s[e][1] + s[e][2] + s[e][3];
            mx = fmaxf(mx, v[e]);
        }
        float sum = 0.f;
#pragma unroll
        for (int e = 0; e < NE; e++) { p[e] = expf(v[e] - mx); sum += p[e]; }
        int i1 = 0;
        for (int e = 1; e < NE; e++) if (v[e] > v[i1]) i1 = e;
        int i2 = (i1 == 0) ? 1 : 0;
        for (int e = 0; e < NE; e++) if (e != i1 && v[e] > v[i2]) i2 = e;
        float inv = 1.f / sum;
        int idx[2] = {i1, i2};
#pragma unroll
        for (int ssel = 0; ssel < 2; ssel++) {
            int e = idx[ssel];
            int pos = atomicAdd(&g_count[e], 1);
            g_tok[e * TMAX + pos] = t;
            g_wt[e * TMAX + pos]  = p[e] * inv;
            g_exp[2 * t + ssel] = e;
            g_pos[2 * t + ssel] = pos;
        }
    }
}

__global__ void offset_kernel() {
    int s = 0;
    for (int e = 0; e < NE; e++) { g_offset[e] = s; s += g_count[e]; }
    g_offset[NE] = s;
}

// ---------------- fused up GEMM: h = silu(X W1^T)*(X W3^T)*wt -------------
// B tile rows [0,64)=W1 cols n0.., [64,128)=W3 same cols. Warps 0-3 -> u1,
// warps 4-7 -> u3 at identical fragment coords; epilogue exchanges u3.
// grid: (INTER/64=22, 32, NE+1)
__global__ void __launch_bounds__(256, 2) gemm_up(int T) {
    int e = blockIdx.z;
    bool se = (e == NE);
    int count = se ? T : g_count[e];
    int row0 = blockIdx.y * 128;
    if (row0 >= count) return;
    int hbase = se ? 2 * T : g_offset[e];
    const __half* W1h = se ? g_sw1h : g_w1h + (size_t)e * INTER * DIM;
    const __half* W3h = se ? g_sw3h : g_w3h + (size_t)e * INTER * DIM;
    int n0 = blockIdx.x * 64;

    extern __shared__ __align__(128) char smem[];
    __shared__ int stok[128];
    __shared__ float swt[128];
    int tid = threadIdx.x, wid = tid >> 5, lane = tid & 31;
    if (tid < 128) {
        int r = row0 + tid;
        int rc = (r < count) ? r : count - 1;
        stok[tid] = se ? rc : g_tok[e * TMAX + rc];
        swt[tid]  = (se || r >= count) ? 1.f : g_wt[e * TMAX + r];
    }
    __syncthreads();

    uint32_t sb = smem_u32(smem);
    uint32_t soff[2], aoff[2];
    const __half* bptr[2];
#pragma unroll
    for (int j = 0; j < 2; j++) {
        int chunk = tid + j * 256;
        int r = chunk >> 2, c4 = chunk & 3;
        soff[j] = toff((uint32_t)r, (uint32_t)c4);
        aoff[j] = (uint32_t)stok[r] * DIM + c4 * 8;
        bptr[j] = ((r < 64) ? (W1h + (size_t)(n0 + r) * DIM)
                            : (W3h + (size_t)(n0 + r - 64) * DIM)) + c4 * 8;
    }

    const int NIT = DIM / KC;  // 64
    auto issue = [&](int itn) {
        if (itn < NIT) {
            uint32_t db = sb + (uint32_t)(itn & (NST - 1)) * STAGE;
            int kk = itn * KC;
#pragma unroll
            for (int j = 0; j < 2; j++) {
                cpa16(db + soff[j],         g_xh + aoff[j] + kk);
                cpa16(db + 8192 + soff[j],  g_xl + aoff[j] + kk);
                cpa16(db + 16384 + soff[j], bptr[j] + kk);
            }
        }
        cpcommit();
    };
    issue(0); issue(1); issue(2);

    int arow = lane & 15, asel = lane >> 4;
    int brow = (lane & 7) + ((lane & 16) >> 1), bsel = (lane >> 3) & 1;
    int wm = (wid & 3) * 32, wn = (wid >> 2) * 64;

    float acc[2][8][4] = {};
    for (int it = 0; it < NIT; it++) {
        cpwait<2>();
        __syncthreads();
        issue(it + 3);
        compute_iter2(acc, sb + (uint32_t)(it & (NST - 1)) * STAGE,
                      wm, wn, arow, asel, brow, bsel);
    }
    cpwait<0>();
    __syncthreads();

    // epilogue: warps 4-7 hold u3 at same (row,col) coords as warps 0-3's u1
    float* ex = (float*)smem;  // 128 x 66 fp32 exchange
    if (wid >= 4) {
#pragma unroll
        for (int mt = 0; mt < 2; mt++)
#pragma unroll
            for (int j = 0; j < 8; j++)
#pragma unroll
                for (int h = 0; h < 2; h++) {
                    int lr = wm + mt * 16 + (lane >> 2) + h * 8;
                    int col = j * 8 + (lane & 3) * 2;
                    ex[lr * 66 + col]     = acc[mt][j][h * 2];
                    ex[lr * 66 + col + 1] = acc[mt][j][h * 2 + 1];
                }
    }
    __syncthreads();
    if (wid < 4) {
#pragma unroll
        for (int mt = 0; mt < 2; mt++)
#pragma unroll
            for (int j = 0; j < 8; j++)
#pragma unroll
                for (int h = 0; h < 2; h++) {
                    int lr = wm + mt * 16 + (lane >> 2) + h * 8;
                    if (row0 + lr < count) {
                        int col = j * 8 + (lane & 3) * 2;
                        float wt = swt[lr];
                        float u1a = acc[mt][j][h * 2],     u3a = ex[lr * 66 + col];
                        float u1b = acc[mt][j][h * 2 + 1], u3b = ex[lr * 66 + col + 1];
                        float ha = (u1a / (1.f + expf(-u1a))) * u3a * wt;
                        float hb = (u1b / (1.f + expf(-u1b))) * u3b * wt;
                        __half2 H = __floats2half2_rn(ha, hb);
                        float2 hf = __half22float2(H);
                        __half2 L = __floats2half2_rn(ha - hf.x, hb - hf.y);
                        size_t o = (size_t)(hbase + row0 + lr) * INTER + n0 + col;
                        *(__half2*)(g_hh + o) = H;
                        *(__half2*)(g_hl + o) = L;
                    }
                }
    }
}

// ---------------- down GEMM: g_d = H W2^T (compacted rows, plain stores) --
// grid: (DIM/128=16, 32, NE+1); z==NE => shared expert
__global__ void __launch_bounds__(256, 2) gemm_down(int T) {
    int z = blockIdx.z;
    bool se = (z == NE);
    int count = se ? T : g_count[z];
    int row0 = blockIdx.y * 128;
    if (row0 >= count) return;
    int hbase = se ? 2 * T : g_offset[z];
    const __half* Bh = se ? g_sw2h : g_w2h + (size_t)z * DIM * INTER;
    int n0 = blockIdx.x * 128;

    extern __shared__ __align__(128) char smem[];
    int tid = threadIdx.x, wid = tid >> 5, lane = tid & 31;

    uint32_t sb = smem_u32(smem);
    uint32_t soff[2], aoff[2];
    const __half* bptr[2];
#pragma unroll
    for (int j = 0; j < 2; j++) {
        int chunk = tid + j * 256;
        int r = chunk >> 2, c4 = chunk & 3;
        soff[j] = toff((uint32_t)r, (uint32_t)c4);
        int rr = row0 + r;
        int hr = hbase + ((rr < count) ? rr : count - 1);
        aoff[j] = (uint32_t)hr * INTER + c4 * 8;
        bptr[j] = Bh + (size_t)(n0 + r) * INTER + c4 * 8;
    }

    const int NIT = INTER / KC;  // 44
    auto issue = [&](int itn) {
        if (itn < NIT) {
            uint32_t db = sb + (uint32_t)(itn & (NST - 1)) * STAGE;
            int kk = itn * KC;
#pragma unroll
            for (int j = 0; j < 2; j++) {
                cpa16(db + soff[j],         g_hh + aoff[j] + kk);
                cpa16(db + 8192 + soff[j],  g_hl + aoff[j] + kk);
                cpa16(db + 16384 + soff[j], bptr[j] + kk);
            }
        }
        cpcommit();
    };
    issue(0); issue(1); issue(2);

    int arow = lane & 15, asel = lane >> 4;
    int brow = (lane & 7) + ((lane & 16) >> 1), bsel = (lane >> 3) & 1;
    int wm = (wid & 3) * 32, wn = (wid >> 2) * 64;

    float acc[2][8][4] = {};
    for (int it = 0; it < NIT; it++) {
        cpwait<2>();
        __syncthreads();
        issue(it + 3);
        compute_iter2(acc, sb + (uint32_t)(it & (NST - 1)) * STAGE,
                      wm, wn, arow, asel, brow, bsel);
    }

#pragma unroll
    for (int mt = 0; mt < 2; mt++)
#pragma unroll
        for (int j = 0; j < 8; j++)
#pragma unroll
            for (int h = 0; h < 2; h++) {
                int lr = wm + mt * 16 + (lane >> 2) + h * 8;
                if (row0 + lr < count) {
                    int col = n0 + wn + j * 8 + (lane & 3) * 2;
                    size_t ob = (size_t)(hbase + row0 + lr) * DIM + col;
                    *(float2*)(g_d + ob) =
                        make_float2(acc[mt][j][h * 2], acc[mt][j][h * 2 + 1]);
                }
            }
}

// ---------------- combine: out[t] = shared + routed1 + routed2 ------------
__global__ void combine_kernel(float* __restrict__ out, int T) {
    int t = blockIdx.x;
    int r1 = g_offset[g_exp[2 * t]]     + g_pos[2 * t];
    int r2 = g_offset[g_exp[2 * t + 1]] + g_pos[2 * t + 1];
    const float4* ps = (const float4*)(g_d + (size_t)(2 * T + t) * DIM);
    const float4* p1 = (const float4*)(g_d + (size_t)r1 * DIM);
    const float4* p2 = (const float4*)(g_d + (size_t)r2 * DIM);
    float4* po = (float4*)(out + (size_t)t * DIM);
#pragma unroll
    for (int q = 0; q < 2; q++) {
        int c = threadIdx.x + q * 256;  // 512 float4 per row
        float4 a = ps[c], b = p1[c], d = p2[c];
        po[c] = make_float4(a.x + b.x + d.x, a.y + b.y + d.y,
                            a.z + b.z + d.z, a.w + b.w + d.w);
    }
}

// ---------------- entry point ----------------------------------------------
extern "C" void kernel_launch(void* const* d_in, const int* in_sizes, int n_in,
                              void* d_out, int out_size) {
    const float* x   = (const float*)d_in[0];
    const float* gw  = (const float*)d_in[1];
    const float* w1  = (const float*)d_in[2];
    const float* w3  = (const float*)d_in[3];
    const float* w2  = (const float*)d_in[4];
    const float* sw1 = (const float*)d_in[5];
    const float* sw3 = (const float*)d_in[6];
    const float* sw2 = (const float*)d_in[7];
    float* out = (float*)d_out;

    int T = in_sizes[0] / DIM;  // 4096

    const int SM = NST * STAGE;  // 96 KB
    cudaFuncSetAttribute(gemm_up,   cudaFuncAttributeMaxDynamicSharedMemorySize, SM);
    cudaFuncSetAttribute(gemm_down, cudaFuncAttributeMaxDynamicSharedMemorySize, SM);

    // lazily created once (on the non-captured correctness call); reused in capture
    static cudaStream_t aux = 0;
    static cudaEvent_t  evF = 0, evJ = 0;
    if (!aux) {
        cudaStreamCreateWithFlags(&aux, cudaStreamNonBlocking);
        cudaEventCreateWithFlags(&evF, cudaEventDisableTiming);
        cudaEventCreateWithFlags(&evJ, cudaEventDisableTiming);
    }

    __half *xh, *xl, *w1h, *w3h, *w2h, *s1h, *s3h, *s2h;
    cudaGetSymbolAddress((void**)&xh,  g_xh);
    cudaGetSymbolAddress((void**)&xl,  g_xl);
    cudaGetSymbolAddress((void**)&w1h, g_w1h);
    cudaGetSymbolAddress((void**)&w3h, g_w3h);
    cudaGetSymbolAddress((void**)&w2h, g_w2h);
    cudaGetSymbolAddress((void**)&s1h, g_sw1h);
    cudaGetSymbolAddress((void**)&s3h, g_sw3h);
    cudaGetSymbolAddress((void**)&s2h, g_sw2h);

    int nw4 = NE * INTER * DIM / 4;
    int ns4 = INTER * DIM / 4;

    // fork: w2/sw2 converts run on aux, overlapping gate/converts/gemm_up
    cudaEventRecord(evF, 0);
    cudaStreamWaitEvent(aux, evF, 0);
    cvt_hi_kernel<<<(nw4 + 255) / 256, 256, 0, aux>>>((const float4*)w2, (uint2*)w2h, nw4);
    cvt_hi_kernel<<<(ns4 + 255) / 256, 256, 0, aux>>>((const float4*)sw2, (uint2*)s2h, ns4);
    cudaEventRecord(evJ, aux);

    // gating (fp32, exact routing)
    reset_kernel<<<1, 32>>>();
    gate_kernel<<<T, 128>>>(x, gw, T);
    offset_kernel<<<1, 1>>>();

    // operand conversion (main stream: inputs to gemm_up)
    int nx4 = T * DIM / 4;
    cvt_hilo_kernel<<<(nx4 + 255) / 256, 256>>>((const float4*)x, (uint2*)xh, (uint2*)xl, nx4);
    cvt_hi_kernel<<<(nw4 + 255) / 256, 256>>>((const float4*)w1, (uint2*)w1h, nw4);
    cvt_hi_kernel<<<(nw4 + 255) / 256, 256>>>((const float4*)w3, (uint2*)w3h, nw4);
    cvt_hi_kernel<<<(ns4 + 255) / 256, 256>>>((const float4*)sw1, (uint2*)s1h, ns4);
    cvt_hi_kernel<<<(ns4 + 255) / 256, 256>>>((const float4*)sw3, (uint2*)s3h, ns4);

    dim3 gup(INTER / 64, (T + 127) / 128, NE + 1);
    gemm_up<<<gup, 256, SM>>>(T);

    // join: down needs w2h/sw2h
    cudaStreamWaitEvent(0, evJ, 0);

    dim3 gdn(DIM / 128, (T + 127) / 128, NE + 1);
    gemm_down<<<gdn, 256, SM>>>(T);

    combine_kernel<<<T, 256>>>(out, T);
}

// round 8
// speedup vs baseline: 1.1937x; 1.1937x over previous
#include <cuda_runtime.h>
#include <cuda_fp16.h>
#include <math.h>
#include <stdint.h>

#define DIM   2048
#define INTER 1408
#define NE    15
#define TMAX  4096
#define KC    32
// up stage layout (bytes): AH[0,8K) AL[8K,16K) BH[16K,24K)
#define STAGE_U 24576
// down stage layout: AH[0,8K) BH[8K,16K)
#define STAGE_D 16384
#define NST   4

// ---------------- device scratch ----------------
__device__ int   g_count[NE];
__device__ int   g_offset[NE + 1];
__device__ int   g_tok[NE * TMAX];
__device__ float g_wt[NE * TMAX];
__device__ int   g_exp[2 * TMAX];
__device__ int   g_pos[2 * TMAX];
__device__ __half g_xh[(size_t)TMAX * DIM];
__device__ __half g_xl[(size_t)TMAX * DIM];
__device__ __half g_w1h[(size_t)NE * INTER * DIM];
__device__ __half g_w3h[(size_t)NE * INTER * DIM];
__device__ __half g_w2h[(size_t)NE * DIM * INTER];
__device__ __half g_sw1h[(size_t)INTER * DIM];
__device__ __half g_sw3h[(size_t)INTER * DIM];
__device__ __half g_sw2h[(size_t)DIM * INTER];
__device__ __half g_hh[(size_t)3 * TMAX * INTER];
__device__ float  g_d[(size_t)3 * TMAX * DIM];   // down results, compacted rows

// ---------------- helpers ----------------
__device__ __forceinline__ uint32_t smem_u32(const void* p) {
    uint32_t a;
    asm("{ .reg .u64 t; cvta.to.shared.u64 t, %1; cvt.u32.u64 %0, t; }" : "=r"(a) : "l"(p));
    return a;
}
// swizzled byte offset inside a 128x32 fp16 tile (64B rows, 4 chunks of 16B)
__device__ __forceinline__ uint32_t toff(uint32_t r, uint32_t c) {
    return r * 64u + ((c ^ ((r >> 1) & 3u)) << 4);
}
__device__ __forceinline__ void ldsm4(uint32_t r[4], uint32_t a) {
    asm volatile("ldmatrix.sync.aligned.m8n8.x4.shared.b16 {%0,%1,%2,%3},[%4];"
                 : "=r"(r[0]), "=r"(r[1]), "=r"(r[2]), "=r"(r[3]) : "r"(a));
}
__device__ __forceinline__ void mma_f16(float c[4], const uint32_t a[4], const uint32_t b[2]) {
    asm volatile("mma.sync.aligned.m16n8k16.row.col.f32.f16.f16.f32 "
                 "{%0,%1,%2,%3},{%4,%5,%6,%7},{%8,%9},{%0,%1,%2,%3};"
                 : "+f"(c[0]), "+f"(c[1]), "+f"(c[2]), "+f"(c[3])
                 : "r"(a[0]), "r"(a[1]), "r"(a[2]), "r"(a[3]), "r"(b[0]), "r"(b[1]));
}
__device__ __forceinline__ void cpa16(uint32_t s, const void* g) {
    asm volatile("cp.async.cg.shared.global [%0], [%1], 16;" :: "r"(s), "l"(g));
}
__device__ __forceinline__ void cpcommit() { asm volatile("cp.async.commit_group;"); }
template <int N> __device__ __forceinline__ void cpwait() {
    asm volatile("cp.async.wait_group %0;" :: "n"(N));
}

// one k-chunk, 2-term split: c += ah*bh + al*bh (up)
__device__ __forceinline__ void compute_iter2(float acc[2][8][4], uint32_t base,
                                              int wm, int wn, int arow, int asel,
                                              int brow, int bsel) {
#pragma unroll
    for (int ks = 0; ks < 2; ks++) {
        uint32_t ah[2][4], al[2][4];
#pragma unroll
        for (int mt = 0; mt < 2; mt++) {
            uint32_t ao = toff((uint32_t)(wm + mt * 16 + arow), (uint32_t)(ks * 2 + asel));
            ldsm4(ah[mt], base + ao);
            ldsm4(al[mt], base + 8192 + ao);
        }
#pragma unroll
        for (int np = 0; np < 4; np++) {
            uint32_t bo = toff((uint32_t)(wn + np * 16 + brow), (uint32_t)(ks * 2 + bsel));
            uint32_t bh[4];
            ldsm4(bh, base + 16384 + bo);
#pragma unroll
            for (int mt = 0; mt < 2; mt++)
#pragma unroll
                for (int ns = 0; ns < 2; ns++) {
                    float* c = acc[mt][np * 2 + ns];
                    mma_f16(c, ah[mt], bh + ns * 2);
                    mma_f16(c, al[mt], bh + ns * 2);
                }
        }
    }
}

// one k-chunk, 1-term: c += ah*bh (down)
__device__ __forceinline__ void compute_iter1(float acc[2][8][4], uint32_t base,
                                              int wm, int wn, int arow, int asel,
                                              int brow, int bsel) {
#pragma unroll
    for (int ks = 0; ks < 2; ks++) {
        uint32_t ah[2][4];
#pragma unroll
        for (int mt = 0; mt < 2; mt++) {
            uint32_t ao = toff((uint32_t)(wm + mt * 16 + arow), (uint32_t)(ks * 2 + asel));
            ldsm4(ah[mt], base + ao);
        }
#pragma unroll
        for (int np = 0; np < 4; np++) {
            uint32_t bo = toff((uint32_t)(wn + np * 16 + brow), (uint32_t)(ks * 2 + bsel));
            uint32_t bh[4];
            ldsm4(bh, base + 8192 + bo);
#pragma unroll
            for (int mt = 0; mt < 2; mt++)
#pragma unroll
                for (int ns = 0; ns < 2; ns++)
                    mma_f16(acc[mt][np * 2 + ns], ah[mt], bh + ns * 2);
        }
    }
}

// ---------------- converts (4 elems/thread, coalesced) ----------------
__global__ void cvt_hi_kernel(const float4* __restrict__ in, uint2* __restrict__ hi, int n4) {
    int i = blockIdx.x * 1024 + threadIdx.x;
#pragma unroll
    for (int j = 0; j < 4; j++, i += 256) {
        if (i < n4) {
            float4 v = in[i];
            __half2 a = __floats2half2_rn(v.x, v.y), b = __floats2half2_rn(v.z, v.w);
            hi[i] = make_uint2(*(uint32_t*)&a, *(uint32_t*)&b);
        }
    }
}
__global__ void cvt_hilo_kernel(const float4* __restrict__ in, uint2* __restrict__ hi,
                                uint2* __restrict__ lo, int n4) {
    int i = blockIdx.x * 1024 + threadIdx.x;
#pragma unroll
    for (int j = 0; j < 4; j++, i += 256) {
        if (i < n4) {
            float4 v = in[i];
            __half2 a = __floats2half2_rn(v.x, v.y), b = __floats2half2_rn(v.z, v.w);
            float2 fa = __half22float2(a), fb = __half22float2(b);
            __half2 la = __floats2half2_rn(v.x - fa.x, v.y - fa.y);
            __half2 lb = __floats2half2_rn(v.z - fb.x, v.w - fb.y);
            hi[i] = make_uint2(*(uint32_t*)&a, *(uint32_t*)&b);
            lo[i] = make_uint2(*(uint32_t*)&la, *(uint32_t*)&lb);
        }
    }
}

// ---------------- gating: warp per token ----------------
__global__ void reset_kernel() { if (threadIdx.x < NE) g_count[threadIdx.x] = 0; }

__global__ void gate_kernel(const float* __restrict__ x,
                            const float* __restrict__ gw, int T) {
    int warp = threadIdx.x >> 5, lane = threadIdx.x & 31;
    int t = blockIdx.x * 8 + warp;
    if (t >= T) return;
    const float4* xt = (const float4*)(x + (size_t)t * DIM);
    const float4* gwv = (const float4*)gw;
    float acc[NE];
#pragma unroll
    for (int e = 0; e < NE; e++) acc[e] = 0.f;
    for (int k = lane; k < DIM / 4; k += 32) {
        float4 xv = xt[k];
#pragma unroll
        for (int e = 0; e < NE; e++) {
            float4 wv = gwv[e * (DIM / 4) + k];
            acc[e] += xv.x * wv.x + xv.y * wv.y + xv.z * wv.z + xv.w * wv.w;
        }
    }
#pragma unroll
    for (int e = 0; e < NE; e++)
#pragma unroll
        for (int o = 16; o > 0; o >>= 1)
            acc[e] += __shfl_xor_sync(0xffffffffu, acc[e], o);
    if (lane == 0) {
        float mx = -1e30f;
#pragma unroll
        for (int e = 0; e < NE; e++) mx = fmaxf(mx, acc[e]);
        float p[NE], sum = 0.f;
#pragma unroll
        for (int e = 0; e < NE; e++) { p[e] = expf(acc[e] - mx); sum += p[e]; }
        int i1 = 0;
        for (int e = 1; e < NE; e++) if (acc[e] > acc[i1]) i1 = e;
        int i2 = (i1 == 0) ? 1 : 0;
        for (int e = 0; e < NE; e++) if (e != i1 && acc[e] > acc[i2]) i2 = e;
        float inv = 1.f / sum;
        int idx[2] = {i1, i2};
#pragma unroll
        for (int ssel = 0; ssel < 2; ssel++) {
            int e = idx[ssel];
            int pos = atomicAdd(&g_count[e], 1);
            g_tok[e * TMAX + pos] = t;
            g_wt[e * TMAX + pos]  = p[e] * inv;
            g_exp[2 * t + ssel] = e;
            g_pos[2 * t + ssel] = pos;
        }
    }
}

__global__ void offset_kernel() {
    int s = 0;
    for (int e = 0; e < NE; e++) { g_offset[e] = s; s += g_count[e]; }
    g_offset[NE] = s;
}

// ---------------- fused up GEMM: h = silu(X W1^T)*(X W3^T)*wt -------------
// grid: (INTER/64=22, 32, NE+1); z==NE => shared expert
__global__ void __launch_bounds__(256, 2) gemm_up(int T) {
    int e = blockIdx.z;
    bool se = (e == NE);
    int count = se ? T : g_count[e];
    int row0 = blockIdx.y * 128;
    if (row0 >= count) return;
    int hbase = se ? 2 * T : g_offset[e];
    const __half* W1h = se ? g_sw1h : g_w1h + (size_t)e * INTER * DIM;
    const __half* W3h = se ? g_sw3h : g_w3h + (size_t)e * INTER * DIM;
    int n0 = blockIdx.x * 64;

    extern __shared__ __align__(128) char smem[];
    __shared__ int stok[128];
    __shared__ float swt[128];
    int tid = threadIdx.x, wid = tid >> 5, lane = tid & 31;
    if (tid < 128) {
        int r = row0 + tid;
        int rc = (r < count) ? r : count - 1;
        stok[tid] = se ? rc : g_tok[e * TMAX + rc];
        swt[tid]  = (se || r >= count) ? 1.f : g_wt[e * TMAX + r];
    }
    __syncthreads();

    uint32_t sb = smem_u32(smem);
    uint32_t soff[2], aoff[2];
    const __half* bptr[2];
#pragma unroll
    for (int j = 0; j < 2; j++) {
        int chunk = tid + j * 256;
        int r = chunk >> 2, c4 = chunk & 3;
        soff[j] = toff((uint32_t)r, (uint32_t)c4);
        aoff[j] = (uint32_t)stok[r] * DIM + c4 * 8;
        bptr[j] = ((r < 64) ? (W1h + (size_t)(n0 + r) * DIM)
                            : (W3h + (size_t)(n0 + r - 64) * DIM)) + c4 * 8;
    }

    const int NIT = DIM / KC;  // 64
    auto issue = [&](int itn) {
        if (itn < NIT) {
            uint32_t db = sb + (uint32_t)(itn & (NST - 1)) * STAGE_U;
            int kk = itn * KC;
#pragma unroll
            for (int j = 0; j < 2; j++) {
                cpa16(db + soff[j],         g_xh + aoff[j] + kk);
                cpa16(db + 8192 + soff[j],  g_xl + aoff[j] + kk);
                cpa16(db + 16384 + soff[j], bptr[j] + kk);
            }
        }
        cpcommit();
    };
    issue(0); issue(1); issue(2);

    int arow = lane & 15, asel = lane >> 4;
    int brow = (lane & 7) + ((lane & 16) >> 1), bsel = (lane >> 3) & 1;
    int wm = (wid & 3) * 32, wn = (wid >> 2) * 64;

    float acc[2][8][4] = {};
    for (int it = 0; it < NIT; it++) {
        cpwait<2>();
        __syncthreads();
        issue(it + 3);
        compute_iter2(acc, sb + (uint32_t)(it & (NST - 1)) * STAGE_U,
                      wm, wn, arow, asel, brow, bsel);
    }
    cpwait<0>();
    __syncthreads();

    // epilogue: warps 4-7 hold u3 at same (row,col) coords as warps 0-3's u1
    float* ex = (float*)smem;  // 128 x 66 fp32 exchange
    if (wid >= 4) {
#pragma unroll
        for (int mt = 0; mt < 2; mt++)
#pragma unroll
            for (int j = 0; j < 8; j++)
#pragma unroll
                for (int h = 0; h < 2; h++) {
                    int lr = wm + mt * 16 + (lane >> 2) + h * 8;
                    int col = j * 8 + (lane & 3) * 2;
                    ex[lr * 66 + col]     = acc[mt][j][h * 2];
                    ex[lr * 66 + col + 1] = acc[mt][j][h * 2 + 1];
                }
    }
    __syncthreads();
    if (wid < 4) {
#pragma unroll
        for (int mt = 0; mt < 2; mt++)
#pragma unroll
            for (int j = 0; j < 8; j++)
#pragma unroll
                for (int h = 0; h < 2; h++) {
                    int lr = wm + mt * 16 + (lane >> 2) + h * 8;
                    if (row0 + lr < count) {
                        int col = j * 8 + (lane & 3) * 2;
                        float wt = swt[lr];
                        float u1a = acc[mt][j][h * 2],     u3a = ex[lr * 66 + col];
                        float u1b = acc[mt][j][h * 2 + 1], u3b = ex[lr * 66 + col + 1];
                        float ha = (u1a / (1.f + expf(-u1a))) * u3a * wt;
                        float hb = (u1b / (1.f + expf(-u1b))) * u3b * wt;
                        __half2 H = __floats2half2_rn(ha, hb);
                        size_t o = (size_t)(hbase + row0 + lr) * INTER + n0 + col;
                        *(__half2*)(g_hh + o) = H;
                    }
                }
    }
}

// ---------------- down GEMM (1-term): g_d = H_hi W2h^T ---------------------
// grid: (DIM/128=16, 32, NE+1); z==NE => shared expert
__global__ void __launch_bounds__(256, 2) gemm_down(int T) {
    int z = blockIdx.z;
    bool se = (z == NE);
    int count = se ? T : g_count[z];
    int row0 = blockIdx.y * 128;
    if (row0 >= count) return;
    int hbase = se ? 2 * T : g_offset[z];
    const __half* Bh = se ? g_sw2h : g_w2h + (size_t)z * DIM * INTER;
    int n0 = blockIdx.x * 128;

    extern __shared__ __align__(128) char smem[];
    int tid = threadIdx.x, wid = tid >> 5, lane = tid & 31;

    uint32_t sb = smem_u32(smem);
    uint32_t soff[2], aoff[2];
    const __half* bptr[2];
#pragma unroll
    for (int j = 0; j < 2; j++) {
        int chunk = tid + j * 256;
        int r = chunk >> 2, c4 = chunk & 3;
        soff[j] = toff((uint32_t)r, (uint32_t)c4);
        int rr = row0 + r;
        int hr = hbase + ((rr < count) ? rr : count - 1);
        aoff[j] = (uint32_t)hr * INTER + c4 * 8;
        bptr[j] = Bh + (size_t)(n0 + r) * INTER + c4 * 8;
    }

    const int NIT = INTER / KC;  // 44
    auto issue = [&](int itn) {
        if (itn < NIT) {
            uint32_t db = sb + (uint32_t)(itn & (NST - 1)) * STAGE_D;
            int kk = itn * KC;
#pragma unroll
            for (int j = 0; j < 2; j++) {
                cpa16(db + soff[j],        g_hh + aoff[j] + kk);
                cpa16(db + 8192 + soff[j], bptr[j] + kk);
            }
        }
        cpcommit();
    };
    issue(0); issue(1); issue(2);

    int arow = lane & 15, asel = lane >> 4;
    int brow = (lane & 7) + ((lane & 16) >> 1), bsel = (lane >> 3) & 1;
    int wm = (wid & 3) * 32, wn = (wid >> 2) * 64;

    float acc[2][8][4] = {};
    for (int it = 0; it < NIT; it++) {
        cpwait<2>();
        __syncthreads();
        issue(it + 3);
        compute_iter1(acc, sb + (uint32_t)(it & (NST - 1)) * STAGE_D,
                      wm, wn, arow, asel, brow, bsel);
    }

#pragma unroll
    for (int mt = 0; mt < 2; mt++)
#pragma unroll
        for (int j = 0; j < 8; j++)
#pragma unroll
            for (int h = 0; h < 2; h++) {
                int lr = wm + mt * 16 + (lane >> 2) + h * 8;
                if (row0 + lr < count) {
                    int col = n0 + wn + j * 8 + (lane & 3) * 2;
                    size_t ob = (size_t)(hbase + row0 + lr) * DIM + col;
                    *(float2*)(g_d + ob) =
                        make_float2(acc[mt][j][h * 2], acc[mt][j][h * 2 + 1]);
                }
            }
}

// ---------------- combine: out[t] = shared + routed1 + routed2 ------------
__global__ void combine_kernel(float* __restrict__ out, int T) {
    int t = blockIdx.x;
    int r1 = g_offset[g_exp[2 * t]]     + g_pos[2 * t];
    int r2 = g_offset[g_exp[2 * t + 1]] + g_pos[2 * t + 1];
    const float4* ps = (const float4*)(g_d + (size_t)(2 * T + t) * DIM);
    const float4* p1 = (const float4*)(g_d + (size_t)r1 * DIM);
    const float4* p2 = (const float4*)(g_d + (size_t)r2 * DIM);
    float4* po = (float4*)(out + (size_t)t * DIM);
#pragma unroll
    for (int q = 0; q < 2; q++) {
        int c = threadIdx.x + q * 256;  // 512 float4 per row
        float4 a = ps[c], b = p1[c], d = p2[c];
        po[c] = make_float4(a.x + b.x + d.x, a.y + b.y + d.y,
                            a.z + b.z + d.z, a.w + b.w + d.w);
    }
}

// ---------------- entry point ----------------------------------------------
extern "C" void kernel_launch(void* const* d_in, const int* in_sizes, int n_in,
                              void* d_out, int out_size) {
    const float* x   = (const float*)d_in[0];
    const float* gw  = (const float*)d_in[1];
    const float* w1  = (const float*)d_in[2];
    const float* w3  = (const float*)d_in[3];
    const float* w2  = (const float*)d_in[4];
    const float* sw1 = (const float*)d_in[5];
    const float* sw3 = (const float*)d_in[6];
    const float* sw2 = (const float*)d_in[7];
    float* out = (float*)d_out;

    int T = in_sizes[0] / DIM;  // 4096

    const int SM_UP = NST * STAGE_U;  // 96 KB
    const int SM_DN = NST * STAGE_D;  // 64 KB
    cudaFuncSetAttribute(gemm_up,   cudaFuncAttributeMaxDynamicSharedMemorySize, SM_UP);
    cudaFuncSetAttribute(gemm_down, cudaFuncAttributeMaxDynamicSharedMemorySize, SM_DN);

    // lazily created once (non-captured correctness call); reused in capture
    static cudaStream_t aux = 0, aux2 = 0;
    static cudaEvent_t  evF = 0, evJ = 0, evG = 0;
    if (!aux) {
        cudaStreamCreateWithFlags(&aux,  cudaStreamNonBlocking);
        cudaStreamCreateWithFlags(&aux2, cudaStreamNonBlocking);
        cudaEventCreateWithFlags(&evF, cudaEventDisableTiming);
        cudaEventCreateWithFlags(&evJ, cudaEventDisableTiming);
        cudaEventCreateWithFlags(&evG, cudaEventDisableTiming);
    }

    __half *xh, *xl, *w1h, *w3h, *w2h, *s1h, *s3h, *s2h;
    cudaGetSymbolAddress((void**)&xh,  g_xh);
    cudaGetSymbolAddress((void**)&xl,  g_xl);
    cudaGetSymbolAddress((void**)&w1h, g_w1h);
    cudaGetSymbolAddress((void**)&w3h, g_w3h);
    cudaGetSymbolAddress((void**)&w2h, g_w2h);
    cudaGetSymbolAddress((void**)&s1h, g_sw1h);
    cudaGetSymbolAddress((void**)&s3h, g_sw3h);
    cudaGetSymbolAddress((void**)&s2h, g_sw2h);

    int nw4 = NE * INTER * DIM / 4;
    int ns4 = INTER * DIM / 4;
    int nx4 = T * DIM / 4;

    // fork point
    cudaEventRecord(evF, 0);

    // aux: w2/sw2 converts (needed only by gemm_down)
    cudaStreamWaitEvent(aux, evF, 0);
    cvt_hi_kernel<<<(nw4 + 1023) / 1024, 256, 0, aux>>>((const float4*)w2, (uint2*)w2h, nw4);
    cvt_hi_kernel<<<(ns4 + 1023) / 1024, 256, 0, aux>>>((const float4*)sw2, (uint2*)s2h, ns4);
    cudaEventRecord(evJ, aux);

    // aux2: gating (needed only by gemm_up)
    cudaStreamWaitEvent(aux2, evF, 0);
    reset_kernel<<<1, 32, 0, aux2>>>();
    gate_kernel<<<(T + 7) / 8, 256, 0, aux2>>>(x, gw, T);
    offset_kernel<<<1, 1, 0, aux2>>>();
    cudaEventRecord(evG, aux2);

    // main: converts feeding gemm_up
    cvt_hilo_kernel<<<(nx4 + 1023) / 1024, 256>>>((const float4*)x, (uint2*)xh, (uint2*)xl, nx4);
    cvt_hi_kernel<<<(nw4 + 1023) / 1024, 256>>>((const float4*)w1, (uint2*)w1h, nw4);
    cvt_hi_kernel<<<(nw4 + 1023) / 1024, 256>>>((const float4*)w3, (uint2*)w3h, nw4);
    cvt_hi_kernel<<<(ns4 + 1023) / 1024, 256>>>((const float4*)sw1, (uint2*)s1h, ns4);
    cvt_hi_kernel<<<(ns4 + 1023) / 1024, 256>>>((const float4*)sw3, (uint2*)s3h, ns4);

    cudaStreamWaitEvent(0, evG, 0);
    dim3 gup(INTER / 64, (T + 127) / 128, NE + 1);
    gemm_up<<<gup, 256, SM_UP>>>(T);

    cudaStreamWaitEvent(0, evJ, 0);
    dim3 gdn(DIM / 128, (T + 127) / 128, NE + 1);
    gemm_down<<<gdn, 256, SM_DN>>>(T);

    combine_kernel<<<T, 256>>>(out, T);
}

// round 9
// speedup vs baseline: 1.6588x; 1.3896x over previous
#include <cuda_runtime.h>
#include <cuda_fp16.h>
#include <math.h>
#include <stdint.h>

#define DIM   2048
#define INTER 1408
#define NE    15
#define TMAX  4096
#define KC    32
// stage layout (bytes): AH[0,8K) BH[8K,16K)
#define STAGE 16384
#define NST   4

// ---------------- device scratch ----------------
__device__ int   g_count[NE];
__device__ int   g_offset[NE + 1];
__device__ int   g_tok[NE * TMAX];
__device__ float g_wt[NE * TMAX];
__device__ int   g_exp[2 * TMAX];
__device__ int   g_pos[2 * TMAX];
__device__ __half g_xh[(size_t)TMAX * DIM];
__device__ __half g_w1h[(size_t)NE * INTER * DIM];
__device__ __half g_w3h[(size_t)NE * INTER * DIM];
__device__ __half g_w2h[(size_t)NE * DIM * INTER];
__device__ __half g_sw1h[(size_t)INTER * DIM];
__device__ __half g_sw3h[(size_t)INTER * DIM];
__device__ __half g_sw2h[(size_t)DIM * INTER];
__device__ __half g_hh[(size_t)3 * TMAX * INTER];
__device__ float  g_d[(size_t)3 * TMAX * DIM];   // down results, compacted rows

// ---------------- helpers ----------------
__device__ __forceinline__ uint32_t smem_u32(const void* p) {
    uint32_t a;
    asm("{ .reg .u64 t; cvta.to.shared.u64 t, %1; cvt.u32.u64 %0, t; }" : "=r"(a) : "l"(p));
    return a;
}
// swizzled byte offset inside a 128x32 fp16 tile (64B rows, 4 chunks of 16B)
__device__ __forceinline__ uint32_t toff(uint32_t r, uint32_t c) {
    return r * 64u + ((c ^ ((r >> 1) & 3u)) << 4);
}
__device__ __forceinline__ void ldsm4(uint32_t r[4], uint32_t a) {
    asm volatile("ldmatrix.sync.aligned.m8n8.x4.shared.b16 {%0,%1,%2,%3},[%4];"
                 : "=r"(r[0]), "=r"(r[1]), "=r"(r[2]), "=r"(r[3]) : "r"(a));
}
__device__ __forceinline__ void mma_f16(float c[4], const uint32_t a[4], const uint32_t b[2]) {
    asm volatile("mma.sync.aligned.m16n8k16.row.col.f32.f16.f16.f32 "
                 "{%0,%1,%2,%3},{%4,%5,%6,%7},{%8,%9},{%0,%1,%2,%3};"
                 : "+f"(c[0]), "+f"(c[1]), "+f"(c[2]), "+f"(c[3])
                 : "r"(a[0]), "r"(a[1]), "r"(a[2]), "r"(a[3]), "r"(b[0]), "r"(b[1]));
}
__device__ __forceinline__ void cpa16(uint32_t s, const void* g) {
    asm volatile("cp.async.cg.shared.global [%0], [%1], 16;" :: "r"(s), "l"(g));
}
__device__ __forceinline__ void cpcommit() { asm volatile("cp.async.commit_group;"); }
template <int N> __device__ __forceinline__ void cpwait() {
    asm volatile("cp.async.wait_group %0;" :: "n"(N));
}

// one k-chunk, 1-term: c += ah*bh
__device__ __forceinline__ void compute_iter1(float acc[2][8][4], uint32_t base,
                                              int wm, int wn, int arow, int asel,
                                              int brow, int bsel) {
#pragma unroll
    for (int ks = 0; ks < 2; ks++) {
        uint32_t ah[2][4];
#pragma unroll
        for (int mt = 0; mt < 2; mt++) {
            uint32_t ao = toff((uint32_t)(wm + mt * 16 + arow), (uint32_t)(ks * 2 + asel));
            ldsm4(ah[mt], base + ao);
        }
#pragma unroll
        for (int np = 0; np < 4; np++) {
            uint32_t bo = toff((uint32_t)(wn + np * 16 + brow), (uint32_t)(ks * 2 + bsel));
            uint32_t bh[4];
            ldsm4(bh, base + 8192 + bo);
#pragma unroll
            for (int mt = 0; mt < 2; mt++)
#pragma unroll
                for (int ns = 0; ns < 2; ns++)
                    mma_f16(acc[mt][np * 2 + ns], ah[mt], bh + ns * 2);
        }
    }
}

// ---------------- converts (4 elems/thread, coalesced) ----------------
__global__ void cvt_hi_kernel(const float4* __restrict__ in, uint2* __restrict__ hi, int n4) {
    int i = blockIdx.x * 1024 + threadIdx.x;
#pragma unroll
    for (int j = 0; j < 4; j++, i += 256) {
        if (i < n4) {
            float4 v = in[i];
            __half2 a = __floats2half2_rn(v.x, v.y), b = __floats2half2_rn(v.z, v.w);
            hi[i] = make_uint2(*(uint32_t*)&a, *(uint32_t*)&b);
        }
    }
}

// ---------------- gating: warp per token ----------------
__global__ void reset_kernel() { if (threadIdx.x < NE) g_count[threadIdx.x] = 0; }

__global__ void gate_kernel(const float* __restrict__ x,
                            const float* __restrict__ gw, int T) {
    int warp = threadIdx.x >> 5, lane = threadIdx.x & 31;
    int t = blockIdx.x * 8 + warp;
    if (t >= T) return;
    const float4* xt = (const float4*)(x + (size_t)t * DIM);
    const float4* gwv = (const float4*)gw;
    float acc[NE];
#pragma unroll
    for (int e = 0; e < NE; e++) acc[e] = 0.f;
    for (int k = lane; k < DIM / 4; k += 32) {
        float4 xv = xt[k];
#pragma unroll
        for (int e = 0; e < NE; e++) {
            float4 wv = gwv[e * (DIM / 4) + k];
            acc[e] += xv.x * wv.x + xv.y * wv.y + xv.z * wv.z + xv.w * wv.w;
        }
    }
#pragma unroll
    for (int e = 0; e < NE; e++)
#pragma unroll
        for (int o = 16; o > 0; o >>= 1)
            acc[e] += __shfl_xor_sync(0xffffffffu, acc[e], o);
    if (lane == 0) {
        float mx = -1e30f;
#pragma unroll
        for (int e = 0; e < NE; e++) mx = fmaxf(mx, acc[e]);
        float p[NE], sum = 0.f;
#pragma unroll
        for (int e = 0; e < NE; e++) { p[e] = expf(acc[e] - mx); sum += p[e]; }
        int i1 = 0;
        for (int e = 1; e < NE; e++) if (acc[e] > acc[i1]) i1 = e;
        int i2 = (i1 == 0) ? 1 : 0;
        for (int e = 0; e < NE; e++) if (e != i1 && acc[e] > acc[i2]) i2 = e;
        float inv = 1.f / sum;
        int idx[2] = {i1, i2};
#pragma unroll
        for (int ssel = 0; ssel < 2; ssel++) {
            int e = idx[ssel];
            int pos = atomicAdd(&g_count[e], 1);
            g_tok[e * TMAX + pos] = t;
            g_wt[e * TMAX + pos]  = p[e] * inv;
            g_exp[2 * t + ssel] = e;
            g_pos[2 * t + ssel] = pos;
        }
    }
}

__global__ void offset_kernel() {
    int s = 0;
    for (int e = 0; e < NE; e++) { g_offset[e] = s; s += g_count[e]; }
    g_offset[NE] = s;
}

// ---------------- fused up GEMM: h = silu(X W1^T)*(X W3^T)*wt -------------
// B tile rows [0,64)=W1 cols n0.., [64,128)=W3 same cols. Warps 0-3 -> u1,
// warps 4-7 -> u3 at identical fragment coords; epilogue exchanges u3.
// grid: (INTER/64=22, 32, NE+1); z==NE => shared expert
__global__ void __launch_bounds__(256, 2) gemm_up(int T) {
    int e = blockIdx.z;
    bool se = (e == NE);
    int count = se ? T : g_count[e];
    int row0 = blockIdx.y * 128;
    if (row0 >= count) return;
    int hbase = se ? 2 * T : g_offset[e];
    const __half* W1h = se ? g_sw1h : g_w1h + (size_t)e * INTER * DIM;
    const __half* W3h = se ? g_sw3h : g_w3h + (size_t)e * INTER * DIM;
    int n0 = blockIdx.x * 64;

    extern __shared__ __align__(128) char smem[];
    __shared__ int stok[128];
    __shared__ float swt[128];
    int tid = threadIdx.x, wid = tid >> 5, lane = tid & 31;
    if (tid < 128) {
        int r = row0 + tid;
        int rc = (r < count) ? r : count - 1;
        stok[tid] = se ? rc : g_tok[e * TMAX + rc];
        swt[tid]  = (se || r >= count) ? 1.f : g_wt[e * TMAX + r];
    }
    __syncthreads();

    uint32_t sb = smem_u32(smem);
    uint32_t soff[2], aoff[2];
    const __half* bptr[2];
#pragma unroll
    for (int j = 0; j < 2; j++) {
        int chunk = tid + j * 256;
        int r = chunk >> 2, c4 = chunk & 3;
        soff[j] = toff((uint32_t)r, (uint32_t)c4);
        aoff[j] = (uint32_t)stok[r] * DIM + c4 * 8;
        bptr[j] = ((r < 64) ? (W1h + (size_t)(n0 + r) * DIM)
                            : (W3h + (size_t)(n0 + r - 64) * DIM)) + c4 * 8;
    }

    const int NIT = DIM / KC;  // 64
    auto issue = [&](int itn) {
        if (itn < NIT) {
            uint32_t db = sb + (uint32_t)(itn & (NST - 1)) * STAGE;
            int kk = itn * KC;
#pragma unroll
            for (int j = 0; j < 2; j++) {
                cpa16(db + soff[j],        g_xh + aoff[j] + kk);
                cpa16(db + 8192 + soff[j], bptr[j] + kk);
            }
        }
        cpcommit();
    };
    issue(0); issue(1); issue(2);

    int arow = lane & 15, asel = lane >> 4;
    int brow = (lane & 7) + ((lane & 16) >> 1), bsel = (lane >> 3) & 1;
    int wm = (wid & 3) * 32, wn = (wid >> 2) * 64;

    float acc[2][8][4] = {};
    for (int it = 0; it < NIT; it++) {
        cpwait<2>();
        __syncthreads();
        issue(it + 3);
        compute_iter1(acc, sb + (uint32_t)(it & (NST - 1)) * STAGE,
                      wm, wn, arow, asel, brow, bsel);
    }
    cpwait<0>();
    __syncthreads();

    // epilogue: warps 4-7 hold u3 at same (row,col) coords as warps 0-3's u1
    float* ex = (float*)smem;  // 128 x 66 fp32 exchange (33.8 KB < 64 KB)
    if (wid >= 4) {
#pragma unroll
        for (int mt = 0; mt < 2; mt++)
#pragma unroll
            for (int j = 0; j < 8; j++)
#pragma unroll
                for (int h = 0; h < 2; h++) {
                    int lr = wm + mt * 16 + (lane >> 2) + h * 8;
                    int col = j * 8 + (lane & 3) * 2;
                    ex[lr * 66 + col]     = acc[mt][j][h * 2];
                    ex[lr * 66 + col + 1] = acc[mt][j][h * 2 + 1];
                }
    }
    __syncthreads();
    if (wid < 4) {
#pragma unroll
        for (int mt = 0; mt < 2; mt++)
#pragma unroll
            for (int j = 0; j < 8; j++)
#pragma unroll
                for (int h = 0; h < 2; h++) {
                    int lr = wm + mt * 16 + (lane >> 2) + h * 8;
                    if (row0 + lr < count) {
                        int col = j * 8 + (lane & 3) * 2;
                        float wt = swt[lr];
                        float u1a = acc[mt][j][h * 2],     u3a = ex[lr * 66 + col];
                        float u1b = acc[mt][j][h * 2 + 1], u3b = ex[lr * 66 + col + 1];
                        float ha = (u1a / (1.f + expf(-u1a))) * u3a * wt;
                        float hb = (u1b / (1.f + expf(-u1b))) * u3b * wt;
                        __half2 H = __floats2half2_rn(ha, hb);
                        size_t o = (size_t)(hbase + row0 + lr) * INTER + n0 + col;
                        *(__half2*)(g_hh + o) = H;
                    }
                }
    }
}

// ---------------- down GEMM (1-term): g_d = H_hi W2h^T ---------------------
// grid: (DIM/128=16, 32, NE+1); z==NE => shared expert
__global__ void __launch_bounds__(256, 2) gemm_down(int T) {
    int z = blockIdx.z;
    bool se = (z == NE);
    int count = se ? T : g_count[z];
    int row0 = blockIdx.y * 128;
    if (row0 >= count) return;
    int hbase = se ? 2 * T : g_offset[z];
    const __half* Bh = se ? g_sw2h : g_w2h + (size_t)z * DIM * INTER;
    int n0 = blockIdx.x * 128;

    extern __shared__ __align__(128) char smem[];
    int tid = threadIdx.x, wid = tid >> 5, lane = tid & 31;

    uint32_t sb = smem_u32(smem);
    uint32_t soff[2], aoff[2];
    const __half* bptr[2];
#pragma unroll
    for (int j = 0; j < 2; j++) {
        int chunk = tid + j * 256;
        int r = chunk >> 2, c4 = chunk & 3;
        soff[j] = toff((uint32_t)r, (uint32_t)c4);
        int rr = row0 + r;
        int hr = hbase + ((rr < count) ? rr : count - 1);
        aoff[j] = (uint32_t)hr * INTER + c4 * 8;
        bptr[j] = Bh + (size_t)(n0 + r) * INTER + c4 * 8;
    }

    const int NIT = INTER / KC;  // 44
    auto issue = [&](int itn) {
        if (itn < NIT) {
            uint32_t db = sb + (uint32_t)(itn & (NST - 1)) * STAGE;
            int kk = itn * KC;
#pragma unroll
            for (int j = 0; j < 2; j++) {
                cpa16(db + soff[j],        g_hh + aoff[j] + kk);
                cpa16(db + 8192 + soff[j], bptr[j] + kk);
            }
        }
        cpcommit();
    };
    issue(0); issue(1); issue(2);

    int arow = lane & 15, asel = lane >> 4;
    int brow = (lane & 7) + ((lane & 16) >> 1), bsel = (lane >> 3) & 1;
    int wm = (wid & 3) * 32, wn = (wid >> 2) * 64;

    float acc[2][8][4] = {};
    for (int it = 0; it < NIT; it++) {
        cpwait<2>();
        __syncthreads();
        issue(it + 3);
        compute_iter1(acc, sb + (uint32_t)(it & (NST - 1)) * STAGE,
                      wm, wn, arow, asel, brow, bsel);
    }

#pragma unroll
    for (int mt = 0; mt < 2; mt++)
#pragma unroll
        for (int j = 0; j < 8; j++)
#pragma unroll
            for (int h = 0; h < 2; h++) {
                int lr = wm + mt * 16 + (lane >> 2) + h * 8;
                if (row0 + lr < count) {
                    int col = n0 + wn + j * 8 + (lane & 3) * 2;
                    size_t ob = (size_t)(hbase + row0 + lr) * DIM + col;
                    *(float2*)(g_d + ob) =
                        make_float2(acc[mt][j][h * 2], acc[mt][j][h * 2 + 1]);
                }
            }
}

// ---------------- combine: out[t] = shared + routed1 + routed2 ------------
__global__ void combine_kernel(float* __restrict__ out, int T) {
    int t = blockIdx.x;
    int r1 = g_offset[g_exp[2 * t]]     + g_pos[2 * t];
    int r2 = g_offset[g_exp[2 * t + 1]] + g_pos[2 * t + 1];
    const float4* ps = (const float4*)(g_d + (size_t)(2 * T + t) * DIM);
    const float4* p1 = (const float4*)(g_d + (size_t)r1 * DIM);
    const float4* p2 = (const float4*)(g_d + (size_t)r2 * DIM);
    float4* po = (float4*)(out + (size_t)t * DIM);
#pragma unroll
    for (int q = 0; q < 2; q++) {
        int c = threadIdx.x + q * 256;  // 512 float4 per row
        float4 a = ps[c], b = p1[c], d = p2[c];
        po[c] = make_float4(a.x + b.x + d.x, a.y + b.y + d.y,
                            a.z + b.z + d.z, a.w + b.w + d.w);
    }
}

// ---------------- entry point ----------------------------------------------
extern "C" void kernel_launch(void* const* d_in, const int* in_sizes, int n_in,
                              void* d_out, int out_size) {
    const float* x   = (const float*)d_in[0];
    const float* gw  = (const float*)d_in[1];
    const float* w1  = (const float*)d_in[2];
    const float* w3  = (const float*)d_in[3];
    const float* w2  = (const float*)d_in[4];
    const float* sw1 = (const float*)d_in[5];
    const float* sw3 = (const float*)d_in[6];
    const float* sw2 = (const float*)d_in[7];
    float* out = (float*)d_out;

    int T = in_sizes[0] / DIM;  // 4096

    const int SM = NST * STAGE;  // 64 KB
    cudaFuncSetAttribute(gemm_up,   cudaFuncAttributeMaxDynamicSharedMemorySize, SM);
    cudaFuncSetAttribute(gemm_down, cudaFuncAttributeMaxDynamicSharedMemorySize, SM);

    // lazily created once (non-captured correctness call); reused in capture
    static cudaStream_t aux = 0, aux2 = 0;
    static cudaEvent_t  evF = 0, evJ = 0, evG = 0;
    if (!aux) {
        cudaStreamCreateWithFlags(&aux,  cudaStreamNonBlocking);
        cudaStreamCreateWithFlags(&aux2, cudaStreamNonBlocking);
        cudaEventCreateWithFlags(&evF, cudaEventDisableTiming);
        cudaEventCreateWithFlags(&evJ, cudaEventDisableTiming);
        cudaEventCreateWithFlags(&evG, cudaEventDisableTiming);
    }

    __half *xh, *w1h, *w3h, *w2h, *s1h, *s3h, *s2h;
    cudaGetSymbolAddress((void**)&xh,  g_xh);
    cudaGetSymbolAddress((void**)&w1h, g_w1h);
    cudaGetSymbolAddress((void**)&w3h, g_w3h);
    cudaGetSymbolAddress((void**)&w2h, g_w2h);
    cudaGetSymbolAddress((void**)&s1h, g_sw1h);
    cudaGetSymbolAddress((void**)&s3h, g_sw3h);
    cudaGetSymbolAddress((void**)&s2h, g_sw2h);

    int nw4 = NE * INTER * DIM / 4;
    int ns4 = INTER * DIM / 4;
    int nx4 = T * DIM / 4;

    // fork point
    cudaEventRecord(evF, 0);

    // aux: w2/sw2 converts (needed only by gemm_down)
    cudaStreamWaitEvent(aux, evF, 0);
    cvt_hi_kernel<<<(nw4 + 1023) / 1024, 256, 0, aux>>>((const float4*)w2, (uint2*)w2h, nw4);
    cvt_hi_kernel<<<(ns4 + 1023) / 1024, 256, 0, aux>>>((const float4*)sw2, (uint2*)s2h, ns4);
    cudaEventRecord(evJ, aux);

    // aux2: gating (needed only by gemm_up)
    cudaStreamWaitEvent(aux2, evF, 0);
    reset_kernel<<<1, 32, 0, aux2>>>();
    gate_kernel<<<(T + 7) / 8, 256, 0, aux2>>>(x, gw, T);
    offset_kernel<<<1, 1, 0, aux2>>>();
    cudaEventRecord(evG, aux2);

    // main: converts feeding gemm_up
    cvt_hi_kernel<<<(nx4 + 1023) / 1024, 256>>>((const float4*)x, (uint2*)xh, nx4);
    cvt_hi_kernel<<<(nw4 + 1023) / 1024, 256>>>((const float4*)w1, (uint2*)w1h, nw4);
    cvt_hi_kernel<<<(nw4 + 1023) / 1024, 256>>>((const float4*)w3, (uint2*)w3h, nw4);
    cvt_hi_kernel<<<(ns4 + 1023) / 1024, 256>>>((const float4*)sw1, (uint2*)s1h, ns4);
    cvt_hi_kernel<<<(ns4 + 1023) / 1024, 256>>>((const float4*)sw3, (uint2*)s3h, ns4);

    cudaStreamWaitEvent(0, evG, 0);
    dim3 gup(INTER / 64, (T + 127) / 128, NE + 1);
    gemm_up<<<gup, 256, SM>>>(T);

    cudaStreamWaitEvent(0, evJ, 0);
    dim3 gdn(DIM / 128, (T + 127) / 128, NE + 1);
    gemm_down<<<gdn, 256, SM>>>(T);

    combine_kernel<<<T, 256>>>(out, T);
}

// round 10
// speedup vs baseline: 1.6631x; 1.0026x over previous
#include <cuda_runtime.h>
#include <cuda_fp16.h>
#include <math.h>
#include <stdint.h>

#define DIM   2048
#define INTER 1408
#define NE    15
#define TMAX  4096
#define KC    32
// stage layout (bytes): AH[0,8K) BH[8K,16K)
#define STAGE 16384
#define NST   6

// ---------------- device scratch ----------------
__device__ int   g_count[NE];
__device__ int   g_offset[NE + 1];
__device__ int   g_tok[NE * TMAX];
__device__ float g_wt[NE * TMAX];
__device__ int   g_exp[2 * TMAX];
__device__ int   g_pos[2 * TMAX];
__device__ __half g_xh[(size_t)TMAX * DIM];
__device__ __half g_w1h[(size_t)NE * INTER * DIM];
__device__ __half g_w3h[(size_t)NE * INTER * DIM];
__device__ __half g_w2h[(size_t)NE * DIM * INTER];
__device__ __half g_sw1h[(size_t)INTER * DIM];
__device__ __half g_sw3h[(size_t)INTER * DIM];
__device__ __half g_sw2h[(size_t)DIM * INTER];
__device__ __half g_hh[(size_t)3 * TMAX * INTER];
__device__ float  g_d[(size_t)3 * TMAX * DIM];   // down results, compacted rows

// ---------------- helpers ----------------
__device__ __forceinline__ uint32_t smem_u32(const void* p) {
    uint32_t a;
    asm("{ .reg .u64 t; cvta.to.shared.u64 t, %1; cvt.u32.u64 %0, t; }" : "=r"(a) : "l"(p));
    return a;
}
// swizzled byte offset inside a 128x32 fp16 tile (64B rows, 4 chunks of 16B)
__device__ __forceinline__ uint32_t toff(uint32_t r, uint32_t c) {
    return r * 64u + ((c ^ ((r >> 1) & 3u)) << 4);
}
__device__ __forceinline__ void ldsm4(uint32_t r[4], uint32_t a) {
    asm volatile("ldmatrix.sync.aligned.m8n8.x4.shared.b16 {%0,%1,%2,%3},[%4];"
                 : "=r"(r[0]), "=r"(r[1]), "=r"(r[2]), "=r"(r[3]) : "r"(a));
}
__device__ __forceinline__ void mma_f16(float c[4], const uint32_t a[4], const uint32_t b[2]) {
    asm volatile("mma.sync.aligned.m16n8k16.row.col.f32.f16.f16.f32 "
                 "{%0,%1,%2,%3},{%4,%5,%6,%7},{%8,%9},{%0,%1,%2,%3};"
                 : "+f"(c[0]), "+f"(c[1]), "+f"(c[2]), "+f"(c[3])
                 : "r"(a[0]), "r"(a[1]), "r"(a[2]), "r"(a[3]), "r"(b[0]), "r"(b[1]));
}
__device__ __forceinline__ void cpa16(uint32_t s, const void* g) {
    asm volatile("cp.async.cg.shared.global [%0], [%1], 16;" :: "r"(s), "l"(g));
}
__device__ __forceinline__ void cpcommit() { asm volatile("cp.async.commit_group;"); }
template <int N> __device__ __forceinline__ void cpwait() {
    asm volatile("cp.async.wait_group %0;" :: "n"(N));
}

// one k-chunk, 1-term: c += ah*bh
__device__ __forceinline__ void compute_iter1(float acc[2][8][4], uint32_t base,
                                              int wm, int wn, int arow, int asel,
                                              int brow, int bsel) {
#pragma unroll
    for (int ks = 0; ks < 2; ks++) {
        uint32_t ah[2][4];
#pragma unroll
        for (int mt = 0; mt < 2; mt++) {
            uint32_t ao = toff((uint32_t)(wm + mt * 16 + arow), (uint32_t)(ks * 2 + asel));
            ldsm4(ah[mt], base + ao);
        }
#pragma unroll
        for (int np = 0; np < 4; np++) {
            uint32_t bo = toff((uint32_t)(wn + np * 16 + brow), (uint32_t)(ks * 2 + bsel));
            uint32_t bh[4];
            ldsm4(bh, base + 8192 + bo);
#pragma unroll
            for (int mt = 0; mt < 2; mt++)
#pragma unroll
                for (int ns = 0; ns < 2; ns++)
                    mma_f16(acc[mt][np * 2 + ns], ah[mt], bh + ns * 2);
        }
    }
}

// ---------------- converts (4 elems/thread, coalesced) ----------------
__global__ void cvt_hi_kernel(const float4* __restrict__ in, uint2* __restrict__ hi, int n4) {
    int i = blockIdx.x * 1024 + threadIdx.x;
#pragma unroll
    for (int j = 0; j < 4; j++, i += 256) {
        if (i < n4) {
            float4 v = in[i];
            __half2 a = __floats2half2_rn(v.x, v.y), b = __floats2half2_rn(v.z, v.w);
            hi[i] = make_uint2(*(uint32_t*)&a, *(uint32_t*)&b);
        }
    }
}

// ---------------- gating: warp per token ----------------
__global__ void reset_kernel() { if (threadIdx.x < NE) g_count[threadIdx.x] = 0; }

__global__ void gate_kernel(const float* __restrict__ x,
                            const float* __restrict__ gw, int T) {
    int warp = threadIdx.x >> 5, lane = threadIdx.x & 31;
    int t = blockIdx.x * 8 + warp;
    if (t >= T) return;
    const float4* xt = (const float4*)(x + (size_t)t * DIM);
    const float4* gwv = (const float4*)gw;
    float acc[NE];
#pragma unroll
    for (int e = 0; e < NE; e++) acc[e] = 0.f;
    for (int k = lane; k < DIM / 4; k += 32) {
        float4 xv = xt[k];
#pragma unroll
        for (int e = 0; e < NE; e++) {
            float4 wv = gwv[e * (DIM / 4) + k];
            acc[e] += xv.x * wv.x + xv.y * wv.y + xv.z * wv.z + xv.w * wv.w;
        }
    }
#pragma unroll
    for (int e = 0; e < NE; e++)
#pragma unroll
        for (int o = 16; o > 0; o >>= 1)
            acc[e] += __shfl_xor_sync(0xffffffffu, acc[e], o);
    if (lane == 0) {
        float mx = -1e30f;
#pragma unroll
        for (int e = 0; e < NE; e++) mx = fmaxf(mx, acc[e]);
        float p[NE], sum = 0.f;
#pragma unroll
        for (int e = 0; e < NE; e++) { p[e] = expf(acc[e] - mx); sum += p[e]; }
        int i1 = 0;
        for (int e = 1; e < NE; e++) if (acc[e] > acc[i1]) i1 = e;
        int i2 = (i1 == 0) ? 1 : 0;
        for (int e = 0; e < NE; e++) if (e != i1 && acc[e] > acc[i2]) i2 = e;
        float inv = 1.f / sum;
        int idx[2] = {i1, i2};
#pragma unroll
        for (int ssel = 0; ssel < 2; ssel++) {
            int e = idx[ssel];
            int pos = atomicAdd(&g_count[e], 1);
            g_tok[e * TMAX + pos] = t;
            g_wt[e * TMAX + pos]  = p[e] * inv;
            g_exp[2 * t + ssel] = e;
            g_pos[2 * t + ssel] = pos;
        }
    }
}

__global__ void offset_kernel() {
    int s = 0;
    for (int e = 0; e < NE; e++) { g_offset[e] = s; s += g_count[e]; }
    g_offset[NE] = s;
}

// ---------------- fused up GEMM: h = silu(X W1^T)*(X W3^T)*wt -------------
// grid: (INTER/64=22, 32, nz); e = z0 + blockIdx.z; e==NE => shared expert
__global__ void __launch_bounds__(256, 2) gemm_up(int T, int z0) {
    int e = z0 + blockIdx.z;
    bool se = (e == NE);
    int count = se ? T : g_count[e];
    int row0 = blockIdx.y * 128;
    if (row0 >= count) return;
    int hbase = se ? 2 * T : g_offset[e];
    const __half* W1h = se ? g_sw1h : g_w1h + (size_t)e * INTER * DIM;
    const __half* W3h = se ? g_sw3h : g_w3h + (size_t)e * INTER * DIM;
    int n0 = blockIdx.x * 64;

    extern __shared__ __align__(128) char smem[];
    __shared__ int stok[128];
    __shared__ float swt[128];
    int tid = threadIdx.x, wid = tid >> 5, lane = tid & 31;
    if (tid < 128) {
        int r = row0 + tid;
        int rc = (r < count) ? r : count - 1;
        stok[tid] = se ? rc : g_tok[e * TMAX + rc];
        swt[tid]  = (se || r >= count) ? 1.f : g_wt[e * TMAX + r];
    }
    __syncthreads();

    uint32_t sb = smem_u32(smem);
    uint32_t soff[2], aoff[2];
    const __half* bptr[2];
#pragma unroll
    for (int j = 0; j < 2; j++) {
        int chunk = tid + j * 256;
        int r = chunk >> 2, c4 = chunk & 3;
        soff[j] = toff((uint32_t)r, (uint32_t)c4);
        aoff[j] = (uint32_t)stok[r] * DIM + c4 * 8;
        bptr[j] = ((r < 64) ? (W1h + (size_t)(n0 + r) * DIM)
                            : (W3h + (size_t)(n0 + r - 64) * DIM)) + c4 * 8;
    }

    const int NIT = DIM / KC;  // 64 (even)
    auto issue = [&](int itn) {
        if (itn < NIT) {
            uint32_t db = sb + (uint32_t)(itn % NST) * STAGE;
            int kk = itn * KC;
#pragma unroll
            for (int j = 0; j < 2; j++) {
                cpa16(db + soff[j],        g_xh + aoff[j] + kk);
                cpa16(db + 8192 + soff[j], bptr[j] + kk);
            }
        }
        cpcommit();
    };
    issue(0); issue(1); issue(2); issue(3);

    int arow = lane & 15, asel = lane >> 4;
    int brow = (lane & 7) + ((lane & 16) >> 1), bsel = (lane >> 3) & 1;
    int wm = (wid & 3) * 32, wn = (wid >> 2) * 64;

    float acc[2][8][4] = {};
    for (int it = 0; it < NIT; it += 2) {
        cpwait<2>();
        __syncthreads();
        issue(it + 4);
        issue(it + 5);
        compute_iter1(acc, sb + (uint32_t)(it % NST) * STAGE,
                      wm, wn, arow, asel, brow, bsel);
        compute_iter1(acc, sb + (uint32_t)((it + 1) % NST) * STAGE,
                      wm, wn, arow, asel, brow, bsel);
    }
    cpwait<0>();
    __syncthreads();

    // epilogue: warps 4-7 hold u3 at same (row,col) coords as warps 0-3's u1
    float* ex = (float*)smem;  // 128 x 66 fp32 exchange (33.8 KB < 96 KB)
    if (wid >= 4) {
#pragma unroll
        for (int mt = 0; mt < 2; mt++)
#pragma unroll
            for (int j = 0; j < 8; j++)
#pragma unroll
                for (int h = 0; h < 2; h++) {
                    int lr = wm + mt * 16 + (lane >> 2) + h * 8;
                    int col = j * 8 + (lane & 3) * 2;
                    ex[lr * 66 + col]     = acc[mt][j][h * 2];
                    ex[lr * 66 + col + 1] = acc[mt][j][h * 2 + 1];
                }
    }
    __syncthreads();
    if (wid < 4) {
#pragma unroll
        for (int mt = 0; mt < 2; mt++)
#pragma unroll
            for (int j = 0; j < 8; j++)
#pragma unroll
                for (int h = 0; h < 2; h++) {
                    int lr = wm + mt * 16 + (lane >> 2) + h * 8;
                    if (row0 + lr < count) {
                        int col = j * 8 + (lane & 3) * 2;
                        float wt = swt[lr];
                        float u1a = acc[mt][j][h * 2],     u3a = ex[lr * 66 + col];
                        float u1b = acc[mt][j][h * 2 + 1], u3b = ex[lr * 66 + col + 1];
                        float ha = (u1a / (1.f + expf(-u1a))) * u3a * wt;
                        float hb = (u1b / (1.f + expf(-u1b))) * u3b * wt;
                        __half2 H = __floats2half2_rn(ha, hb);
                        size_t o = (size_t)(hbase + row0 + lr) * INTER + n0 + col;
                        *(__half2*)(g_hh + o) = H;
                    }
                }
    }
}

// ---------------- down GEMM (1-term): g_d = H_hi W2h^T ---------------------
// grid: (DIM/128=16, 32, nz); z = z0 + blockIdx.z; z==NE => shared expert
__global__ void __launch_bounds__(256, 2) gemm_down(int T, int z0) {
    int z = z0 + blockIdx.z;
    bool se = (z == NE);
    int count = se ? T : g_count[z];
    int row0 = blockIdx.y * 128;
    if (row0 >= count) return;
    int hbase = se ? 2 * T : g_offset[z];
    const __half* Bh = se ? g_sw2h : g_w2h + (size_t)z * DIM * INTER;
    int n0 = blockIdx.x * 128;

    extern __shared__ __align__(128) char smem[];
    int tid = threadIdx.x, wid = tid >> 5, lane = tid & 31;

    uint32_t sb = smem_u32(smem);
    uint32_t soff[2], aoff[2];
    const __half* bptr[2];
#pragma unroll
    for (int j = 0; j < 2; j++) {
        int chunk = tid + j * 256;
        int r = chunk >> 2, c4 = chunk & 3;
        soff[j] = toff((uint32_t)r, (uint32_t)c4);
        int rr = row0 + r;
        int hr = hbase + ((rr < count) ? rr : count - 1);
        aoff[j] = (uint32_t)hr * INTER + c4 * 8;
        bptr[j] = Bh + (size_t)(n0 + r) * INTER + c4 * 8;
    }

    const int NIT = INTER / KC;  // 44 (even)
    auto issue = [&](int itn) {
        if (itn < NIT) {
            uint32_t db = sb + (uint32_t)(itn % NST) * STAGE;
            int kk = itn * KC;
#pragma unroll
            for (int j = 0; j < 2; j++) {
                cpa16(db + soff[j],        g_hh + aoff[j] + kk);
                cpa16(db + 8192 + soff[j], bptr[j] + kk);
            }
        }
        cpcommit();
    };
    issue(0); issue(1); issue(2); issue(3);

    int arow = lane & 15, asel = lane >> 4;
    int brow = (lane & 7) + ((lane & 16) >> 1), bsel = (lane >> 3) & 1;
    int wm = (wid & 3) * 32, wn = (wid >> 2) * 64;

    float acc[2][8][4] = {};
    for (int it = 0; it < NIT; it += 2) {
        cpwait<2>();
        __syncthreads();
        issue(it + 4);
        issue(it + 5);
        compute_iter1(acc, sb + (uint32_t)(it % NST) * STAGE,
                      wm, wn, arow, asel, brow, bsel);
        compute_iter1(acc, sb + (uint32_t)((it + 1) % NST) * STAGE,
                      wm, wn, arow, asel, brow, bsel);
    }

#pragma unroll
    for (int mt = 0; mt < 2; mt++)
#pragma unroll
        for (int j = 0; j < 8; j++)
#pragma unroll
            for (int h = 0; h < 2; h++) {
                int lr = wm + mt * 16 + (lane >> 2) + h * 8;
                if (row0 + lr < count) {
                    int col = n0 + wn + j * 8 + (lane & 3) * 2;
                    size_t ob = (size_t)(hbase + row0 + lr) * DIM + col;
                    *(float2*)(g_d + ob) =
                        make_float2(acc[mt][j][h * 2], acc[mt][j][h * 2 + 1]);
                }
            }
}

// ---------------- combine: out[t] = shared + routed1 + routed2 ------------
__global__ void combine_kernel(float* __restrict__ out, int T) {
    int t = blockIdx.x;
    int r1 = g_offset[g_exp[2 * t]]     + g_pos[2 * t];
    int r2 = g_offset[g_exp[2 * t + 1]] + g_pos[2 * t + 1];
    const float4* ps = (const float4*)(g_d + (size_t)(2 * T + t) * DIM);
    const float4* p1 = (const float4*)(g_d + (size_t)r1 * DIM);
    const float4* p2 = (const float4*)(g_d + (size_t)r2 * DIM);
    float4* po = (float4*)(out + (size_t)t * DIM);
#pragma unroll
    for (int q = 0; q < 2; q++) {
        int c = threadIdx.x + q * 256;  // 512 float4 per row
        float4 a = ps[c], b = p1[c], d = p2[c];
        po[c] = make_float4(a.x + b.x + d.x, a.y + b.y + d.y,
                            a.z + b.z + d.z, a.w + b.w + d.w);
    }
}

// ---------------- entry point ----------------------------------------------
extern "C" void kernel_launch(void* const* d_in, const int* in_sizes, int n_in,
                              void* d_out, int out_size) {
    const float* x   = (const float*)d_in[0];
    const float* gw  = (const float*)d_in[1];
    const float* w1  = (const float*)d_in[2];
    const float* w3  = (const float*)d_in[3];
    const float* w2  = (const float*)d_in[4];
    const float* sw1 = (const float*)d_in[5];
    const float* sw3 = (const float*)d_in[6];
    const float* sw2 = (const float*)d_in[7];
    float* out = (float*)d_out;

    int T = in_sizes[0] / DIM;  // 4096

    const int SM = NST * STAGE;  // 96 KB
    cudaFuncSetAttribute(gemm_up,   cudaFuncAttributeMaxDynamicSharedMemorySize, SM);
    cudaFuncSetAttribute(gemm_down, cudaFuncAttributeMaxDynamicSharedMemorySize, SM);

    // lazily created once (non-captured correctness call); reused in capture
    static cudaStream_t sA = 0, sB = 0, sC = 0;
    static cudaEvent_t  evF = 0, evX = 0, evW2 = 0, evG = 0, evDS = 0;
    if (!sA) {
        cudaStreamCreateWithFlags(&sA, cudaStreamNonBlocking);
        cudaStreamCreateWithFlags(&sB, cudaStreamNonBlocking);
        cudaStreamCreateWithFlags(&sC, cudaStreamNonBlocking);
        cudaEventCreateWithFlags(&evF,  cudaEventDisableTiming);
        cudaEventCreateWithFlags(&evX,  cudaEventDisableTiming);
        cudaEventCreateWithFlags(&evW2, cudaEventDisableTiming);
        cudaEventCreateWithFlags(&evG,  cudaEventDisableTiming);
        cudaEventCreateWithFlags(&evDS, cudaEventDisableTiming);
    }

    __half *xh, *w1h, *w3h, *w2h, *s1h, *s3h, *s2h;
    cudaGetSymbolAddress((void**)&xh,  g_xh);
    cudaGetSymbolAddress((void**)&w1h, g_w1h);
    cudaGetSymbolAddress((void**)&w3h, g_w3h);
    cudaGetSymbolAddress((void**)&w2h, g_w2h);
    cudaGetSymbolAddress((void**)&s1h, g_sw1h);
    cudaGetSymbolAddress((void**)&s3h, g_sw3h);
    cudaGetSymbolAddress((void**)&s2h, g_sw2h);

    int nw4 = NE * INTER * DIM / 4;
    int ns4 = INTER * DIM / 4;
    int nx4 = T * DIM / 4;

    // fork point
    cudaEventRecord(evF, 0);

    // sA: w2/sw2 converts (needed only by down GEMMs)
    cudaStreamWaitEvent(sA, evF, 0);
    cvt_hi_kernel<<<(nw4 + 1023) / 1024, 256, 0, sA>>>((const float4*)w2, (uint2*)w2h, nw4);
    cvt_hi_kernel<<<(ns4 + 1023) / 1024, 256, 0, sA>>>((const float4*)sw2, (uint2*)s2h, ns4);
    cudaEventRecord(evW2, sA);

    // sB: gating (needed only by routed GEMMs)
    cudaStreamWaitEvent(sB, evF, 0);
    reset_kernel<<<1, 32, 0, sB>>>();
    gate_kernel<<<(T + 7) / 8, 256, 0, sB>>>(x, gw, T);
    offset_kernel<<<1, 1, 0, sB>>>();
    cudaEventRecord(evG, sB);

    // main: x + shared-up converts first (unblocks shared chain early)
    cvt_hi_kernel<<<(nx4 + 1023) / 1024, 256>>>((const float4*)x, (uint2*)xh, nx4);
    cvt_hi_kernel<<<(ns4 + 1023) / 1024, 256>>>((const float4*)sw1, (uint2*)s1h, ns4);
    cvt_hi_kernel<<<(ns4 + 1023) / 1024, 256>>>((const float4*)sw3, (uint2*)s3h, ns4);
    cudaEventRecord(evX, 0);

    // sC: shared-expert chain (no gate dependency)
    cudaStreamWaitEvent(sC, evX, 0);
    {
        dim3 gupS(INTER / 64, (T + 127) / 128, 1);
        gemm_up<<<gupS, 256, SM, sC>>>(T, NE);
        cudaStreamWaitEvent(sC, evW2, 0);
        dim3 gdnS(DIM / 128, (T + 127) / 128, 1);
        gemm_down<<<gdnS, 256, SM, sC>>>(T, NE);
        cudaEventRecord(evDS, sC);
    }

    // main: routed weight converts, then routed chain
    cvt_hi_kernel<<<(nw4 + 1023) / 1024, 256>>>((const float4*)w1, (uint2*)w1h, nw4);
    cvt_hi_kernel<<<(nw4 + 1023) / 1024, 256>>>((const float4*)w3, (uint2*)w3h, nw4);

    cudaStreamWaitEvent(0, evG, 0);
    dim3 gupR(INTER / 64, (T + 127) / 128, NE);
    gemm_up<<<gupR, 256, SM>>>(T, 0);

    cudaStreamWaitEvent(0, evW2, 0);
    dim3 gdnR(DIM / 128, (T + 127) / 128, NE);
    gemm_down<<<gdnR, 256, SM>>>(T, 0);

    cudaStreamWaitEvent(0, evDS, 0);
    combine_kernel<<<T, 256>>>(out, T);
}